// round 17
// baseline (speedup 1.0000x reference)
#include <cuda_runtime.h>
#include <math_constants.h>

// Bidirectional Chamfer distance, B=4, N=M=4096, D=3, fp32.
// dist[b,n,m] = |q_n|^2 + |t_m|^2 - 2 q_n.t_m  -- computed ONCE per (n,m),
// serving BOTH directions (R16 compute, at the fma-pipe floor).
// SINGLE persistent launch, all 1024 blocks co-resident (19KB smem -> 12
// CTAs/SM capacity vs 7 needed): s_cand processed as 2x32-target halves.
// Margins merged via atomicMax on monotone keys (0 == +inf sentinel).
// Tail: epoch-based arrival counter (monotonic, no reset, replay-safe);
// first 256 blocks poll, then each sums 128 keys; epoch-ticketed last block
// does the fixed-order 256-sum. Fully deterministic.

#define BATCH   4
#define NPTS    4096
#define THREADS 128
#define QPT     8
#define QBLK    (THREADS * QPT)          // 1024 queries per block
#define NQBLK   (NPTS / QBLK)            // 4
#define TTB     64                       // targets per block
#define HALF    32                       // targets per s_cand pass
#define NTTILE  (NPTS / TTB)             // 64
#define NBLK    (NQBLK * NTTILE * BATCH) // 1024 blocks
#define NKEY    (2 * BATCH * NPTS)       // 32768
#define COLBASE (BATCH * NPTS)           // 16384
#define CSTRIDE 129                      // cand row stride (conflict-free)
#define PSTRIDE 33
#define TAILB   256                      // tail blocks
#define KPT     (NKEY / TAILB)           // 128 keys per tail block

__device__ __align__(16) unsigned int g_key[NKEY];  // zero-init == +inf
__device__ float        g_bsum[TAILB];
__device__ unsigned int g_done;   // monotonic arrival counter (epochs)
__device__ unsigned int g_tick;   // monotonic tail ticket (epochs)

// key(d) = ~f2key(d): monotone DECREASING in d; all finite d -> key > 0.
__device__ __forceinline__ unsigned int dkey(float f) {
    unsigned int u = __float_as_uint(f);
    unsigned int k = (u & 0x80000000u) ? ~u : (u | 0x80000000u);
    return ~k;
}
__device__ __forceinline__ float key2f(unsigned int kk) {
    unsigned int k = ~kk;
    unsigned int u = (k & 0x80000000u) ? (k & 0x7FFFFFFFu) : ~k;
    return __uint_as_float(u);
}

__global__ __launch_bounds__(THREADS)
void chamfer_kernel(const float* __restrict__ src,
                    const float* __restrict__ tgt,
                    float* __restrict__ out) {
    // sXY[t] = ((-2x,-2x),(-2y,-2y)), sZW[t] = ((-2z,-2z),(w,w)), w=|t|^2
    __shared__ ulonglong2 sXY[TTB];
    __shared__ ulonglong2 sZW[TTB];
    __shared__ float      s_cand[HALF * CSTRIDE];  // 16.5 KB (reused 2x)
    __shared__ float      s_part[4 * PSTRIDE];
    __shared__ float      s_wsum[THREADS / 32];

    const int qblk = blockIdx.x;
    const int tt   = blockIdx.y;
    const int b    = blockIdx.z;
    const int tid  = threadIdx.x;
    const int k    = (b * NTTILE + tt) * NQBLK + qblk;   // flat block id

    const float* __restrict__ qb = src + (size_t)b * NPTS * 3;  // rows
    const float* __restrict__ tb = tgt + (size_t)b * NPTS * 3;  // cols

    // ---- load + duplicate-pack this block's 64 targets
    if (tid < TTB) {
        int m = tt * TTB + tid;
        float x = tb[m * 3 + 0], y = tb[m * 3 + 1], z = tb[m * 3 + 2];
        float w = fmaf(x, x, fmaf(y, y, z * z));
        float nx = -2.0f * x, ny = -2.0f * y, nz = -2.0f * z;
        unsigned long long px, py, pz, pw;
        asm("mov.b64 %0, {%1, %1};" : "=l"(px) : "f"(nx));
        asm("mov.b64 %0, {%1, %1};" : "=l"(py) : "f"(ny));
        asm("mov.b64 %0, {%1, %1};" : "=l"(pz) : "f"(nz));
        asm("mov.b64 %0, {%1, %1};" : "=l"(pw) : "f"(w));
        sXY[tid] = make_ulonglong2(px, py);
        sZW[tid] = make_ulonglong2(pz, pw);
    }

    // ---- load 8 queries/thread as 4 f32x2 pairs; |q|^2 packed as chain base
    const int q0 = qblk * QBLK + tid;
    unsigned long long qx2[4], qy2[4], qz2[4], q22[4];
    float rm[QPT];
#pragma unroll
    for (int r = 0; r < 4; r++) {
        int qa = q0 + (2 * r) * THREADS;
        int qc = qa + THREADS;
        float xa = qb[qa * 3 + 0], ya = qb[qa * 3 + 1], za = qb[qa * 3 + 2];
        float xc = qb[qc * 3 + 0], yc = qb[qc * 3 + 1], zc = qb[qc * 3 + 2];
        asm("mov.b64 %0, {%1, %2};" : "=l"(qx2[r]) : "f"(xa), "f"(xc));
        asm("mov.b64 %0, {%1, %2};" : "=l"(qy2[r]) : "f"(ya), "f"(yc));
        asm("mov.b64 %0, {%1, %2};" : "=l"(qz2[r]) : "f"(za), "f"(zc));
        float q2a = fmaf(xa, xa, fmaf(ya, ya, za * za));
        float q2c = fmaf(xc, xc, fmaf(yc, yc, zc * zc));
        asm("mov.b64 %0, {%1, %2};" : "=l"(q22[r]) : "f"(q2a), "f"(q2c));
        rm[2 * r] = CUDART_INF_F;
        rm[2 * r + 1] = CUDART_INF_F;
    }
    __syncthreads();

    // ---- two passes of 32 targets, reusing s_cand
#pragma unroll
    for (int half = 0; half < 2; half++) {
        const int base = half * HALF;

        // per step: 16 packed fma-ops (fma pipe) + 15 FMNMX (alu) + 1 STS
#pragma unroll 4
        for (int t = 0; t < HALF; t++) {
            ulonglong2 xy = sXY[base + t];
            ulonglong2 zw = sZW[base + t];
            float c[4];
#pragma unroll
            for (int r = 0; r < 4; r++) {
                float d0, d1;
                asm("{\n\t"
                    ".reg .b64 d;\n\t"
                    "fma.rn.f32x2 d, %2, %3, %4;\n\t"   // -2z*qz + |q|^2
                    "fma.rn.f32x2 d, %5, %6, d;\n\t"    // -2y*qy
                    "fma.rn.f32x2 d, %7, %8, d;\n\t"    // -2x*qx
                    "add.rn.f32x2 d, d, %9;\n\t"        // + |t|^2
                    "mov.b64 {%0, %1}, d;\n\t"
                    "}"
                    : "=f"(d0), "=f"(d1)
                    : "l"(zw.x), "l"(qz2[r]), "l"(q22[r]),
                      "l"(xy.y), "l"(qy2[r]),
                      "l"(xy.x), "l"(qx2[r]),
                      "l"(zw.y));
                rm[2 * r]     = fminf(rm[2 * r], d0);
                rm[2 * r + 1] = fminf(rm[2 * r + 1], d1);
                c[r] = fminf(d0, d1);
            }
            s_cand[t * CSTRIDE + tid] =
                fminf(fminf(c[0], c[1]), fminf(c[2], c[3]));
        }
        __syncthreads();

        // col-min for these 32 targets: t = tid&31, chunk = tid>>5
        {
            int t = tid & 31, chunk = tid >> 5;
            const float* cr = s_cand + t * CSTRIDE + chunk * 32;
            float v0 = cr[0], v1 = cr[1], v2 = cr[2], v3 = cr[3];
#pragma unroll
            for (int i = 4; i < 32; i += 4) {
                v0 = fminf(v0, cr[i + 0]);
                v1 = fminf(v1, cr[i + 1]);
                v2 = fminf(v2, cr[i + 2]);
                v3 = fminf(v3, cr[i + 3]);
            }
            s_part[chunk * PSTRIDE + t] = fminf(fminf(v0, v1), fminf(v2, v3));
        }
        __syncthreads();
        if (tid < HALF) {
            float v = fminf(fminf(s_part[tid], s_part[PSTRIDE + tid]),
                            fminf(s_part[2 * PSTRIDE + tid],
                                  s_part[3 * PSTRIDE + tid]));
            int m = tt * TTB + base + tid;
            atomicMax(&g_key[COLBASE + b * NPTS + m], dkey(v));
        }
        __syncthreads();   // before next pass overwrites s_cand
    }

    // ---- row-min merges (rm spans both halves)
#pragma unroll
    for (int j = 0; j < QPT; j++)
        atomicMax(&g_key[b * NPTS + q0 + j * THREADS], dkey(rm[j]));

    // ---- arrival (epoch-based, monotonic: no reset, no replay race)
    __threadfence();
    __syncthreads();
    if (tid == 0) {
        unsigned int p = atomicAdd(&g_done, 1u);
        if (k < TAILB) {
            unsigned int target = p - (p % NBLK) + NBLK;  // end of this epoch
            while (*((volatile unsigned int*)&g_done) < target)
                __nanosleep(256);
        }
    }
    if (k >= TAILB) return;   // non-tail blocks exit, freeing SMs
    __syncthreads();
    __threadfence();          // acquire: all blocks' merges visible

    // ---- tail: this block sums 128 final keys (1/thread), resets sentinels
    {
        int e = k * KPT + tid;
        float v = key2f(g_key[e]);
        g_key[e] = 0u;
#pragma unroll
        for (int off = 16; off > 0; off >>= 1)
            v += __shfl_down_sync(0xFFFFFFFFu, v, off);
        if ((tid & 31) == 0) s_wsum[tid >> 5] = v;
        __syncthreads();

        if (tid == 0) {
            float bs = (s_wsum[0] + s_wsum[1]) + (s_wsum[2] + s_wsum[3]);
            g_bsum[k] = bs;
            __threadfence();
            unsigned int p2 = atomicAdd(&g_tick, 1u);
            if ((p2 % TAILB) == TAILB - 1) {   // last tail block this epoch
                __threadfence();
                // fixed-order 4-lane interleaved sum of 256 block sums
                float a0 = 0.f, a1 = 0.f, a2 = 0.f, a3 = 0.f;
                for (int i = 0; i < TAILB; i += 4) {
                    a0 += g_bsum[i + 0];
                    a1 += g_bsum[i + 1];
                    a2 += g_bsum[i + 2];
                    a3 += g_bsum[i + 3];
                }
                out[0] = ((a0 + a1) + (a2 + a3)) / (float)(BATCH * NPTS);
            }
        }
    }
}

extern "C" void kernel_launch(void* const* d_in, const int* in_sizes, int n_in,
                              void* d_out, int out_size) {
    const float* src = (const float*)d_in[0];  // (B, N, 3)
    const float* tgt = (const float*)d_in[1];  // (B, M, 3)
    float* out = (float*)d_out;

    dim3 grid(NQBLK, NTTILE, BATCH);  // 4 x 64 x 4 = 1024 blocks, co-resident
    chamfer_kernel<<<grid, THREADS>>>(src, tgt, out);
}